// round 2
// baseline (speedup 1.0000x reference)
#include <cuda_runtime.h>
#include <cstdint>

// Problem constants
#define CC   32
#define HH   80
#define WW   80
#define KK   4
#define HP   77            // HH-KK+1
#define NP   (HP*HP)       // 5929 patches
#define DD   (CC*KK*KK)    // 512
#define MW   81            // mask width (H+1)
#define EPSF 1e-6f
#define PPAD 6016          // 47*128, padded patch stride (16B-aligned rows)

// ---------------- device scratch (allocation-free rule) ----------------------
__device__ float              g_lowpT [DD * PPAD];   // candidates, k-major [D][Ppad]
__device__ float              g_highTc[DD * PPAD];   // compacted queries, k-major [D][qi]
__device__ float              g_s1[HH * WW];         // per-pixel sum over c of low^2
__device__ float              g_invnorm[NP];
__device__ unsigned char      g_excl[NP];
__device__ unsigned char      g_valid[NP];
__device__ unsigned long long g_keys[NP];
__device__ int                g_qlist[NP];
__device__ int                g_qcount;

// monotone float->uint mapping (order-preserving for all finite floats)
__device__ __forceinline__ unsigned mono(float f) {
    unsigned b = __float_as_uint(f);
    return (b & 0x80000000u) ? ~b : (b | 0x80000000u);
}
// packed f32x2 helpers (sm_103a FFMA2 path — PTX only)
__device__ __forceinline__ unsigned long long pack2(float a) {
    unsigned long long r;
    asm("mov.b64 %0, {%1, %1};" : "=l"(r) : "f"(a));
    return r;
}
__device__ __forceinline__ void fma2(unsigned long long& c,
                                     unsigned long long a, unsigned long long b) {
    asm("fma.rn.f32x2 %0, %1, %2, %0;" : "+l"(c) : "l"(a), "l"(b));
}
__device__ __forceinline__ float2 unpack2(unsigned long long v) {
    float2 f;
    asm("mov.b64 {%0, %1}, %2;" : "=f"(f.x), "=f"(f.y) : "l"(v));
    return f;
}

// ---------------- K1: per-pixel channel sum of squares (+ counter reset) -----
__global__ void sumsq_kernel(const float* __restrict__ low) {
    int pix = blockIdx.x * blockDim.x + threadIdx.x;
    if (pix == 0) g_qcount = 0;
    if (pix >= HH * WW) return;
    float s = 0.f;
    #pragma unroll
    for (int c = 0; c < CC; c++) { float v = low[c * (HH * WW) + pix]; s += v * v; }
    g_s1[pix] = s;
}

// ---------------- K2: extract candidate matrix, k-major [D][Ppad] ------------
__global__ void extractT_kernel(const float* __restrict__ low) {
    int p = blockIdx.x * blockDim.x + threadIdx.x;
    int d = blockIdx.y;
    if (p >= NP) return;
    int pi = p / HP, pj = p % HP;
    int c  = d >> 4, di = (d >> 2) & 3, dj = d & 3;
    g_lowpT[d * PPAD + p] = low[c * (HH * WW) + (pi + di) * WW + (pj + dj)];
}

// ---------------- K3: per-patch stats (norm, excl, valid, compaction) --------
__global__ void stats_kernel(const int* __restrict__ mask) {
    int p = blockIdx.x * blockDim.x + threadIdx.x;
    if (p >= NP) return;
    int pi = p / HP, pj = p % HP;
    float ns = 0.f;
    #pragma unroll
    for (int di = 0; di < KK; di++)
        #pragma unroll
        for (int dj = 0; dj < KK; dj++)
            ns += g_s1[(pi + di) * WW + (pj + dj)];
    g_invnorm[p] = 1.0f / (sqrtf(ns) + EPSF);
    int m00 = mask[pi * MW + pj];
    g_excl[p] = (m00 == 1);
    g_keys[p] = ((unsigned long long)mono(-1e9f) << 32) | 0xFFFFFFFFull; // cand=0 fallback
    int v = (m00 != 0) && (mask[pi * MW + pj + KK] != 0) &&
            (mask[(pi + KK) * MW + pj] != 0) && (mask[(pi + KK) * MW + pj + KK] != 0);
    g_valid[p] = (unsigned char)v;
    if (v) {
        int slot = atomicAdd(&g_qcount, 1);
        g_qlist[slot] = p;
    }
}

// ---------------- K4: gather compacted query matrix, k-major [D][qi] ---------
__global__ void gather_high_kernel(const float* __restrict__ high) {
    int nq = g_qcount;
    int d  = blockIdx.y;
    int c  = d >> 4, di = (d >> 2) & 3, dj = d & 3;
    for (int qi = blockIdx.x * blockDim.x + threadIdx.x; qi < nq;
         qi += gridDim.x * blockDim.x) {
        int p  = g_qlist[qi];
        int pi = p / HP, pj = p % HP;
        g_highTc[d * PPAD + qi] = high[c * (HH * WW) + (pi + di) * WW + (pj + dj)];
    }
}

// ---------------- K5: 128x128 GEMM (FFMA2) + fused argmax --------------------
// 256 threads, 8x8 per thread, k-major smem tiles, packed f32x2 FMAs.
__global__ void __launch_bounds__(256, 1) gemm_argmax_kernel() {
    const int nq = g_qcount;
    const int qb = blockIdx.y;
    if (qb * 128 >= nq) return;            // inactive query-tiles exit immediately
    const int cb = blockIdx.x;

    __shared__ float Ast[16][128];         // k-major query tile
    __shared__ float Bst[16][128];         // k-major candidate tile
    __shared__ int   qs[128];
    __shared__ unsigned long long red[128][16];

    const int tid = threadIdx.x;
    if (tid < 128) {
        int qi = qb * 128 + tid;
        qs[tid] = (qi < nq) ? g_qlist[qi] : -1;
    }

    const int ty = tid >> 4, tx = tid & 15;
    const int lr = tid >> 4;               // loader row 0..15
    const int lc = (tid & 15) * 4;         // loader col chunk

    const float* Abase = g_highTc + qb * 128;
    const float* Bbase = g_lowpT  + cb * 128;

    unsigned long long acc[8][4];
    #pragma unroll
    for (int i = 0; i < 8; i++)
        #pragma unroll
        for (int j = 0; j < 4; j++) acc[i][j] = 0ull;

    // prefetch stage 0
    float4 pa0 = *(const float4*)(Abase + (size_t)lr * PPAD + lc);
    float4 pa1 = *(const float4*)(Abase + (size_t)lr * PPAD + lc + 64);
    float4 pb0 = *(const float4*)(Bbase + (size_t)lr * PPAD + lc);
    float4 pb1 = *(const float4*)(Bbase + (size_t)lr * PPAD + lc + 64);

    for (int s = 0; s < DD / 16; s++) {
        __syncthreads();
        *(float4*)&Ast[lr][lc]      = pa0;
        *(float4*)&Ast[lr][lc + 64] = pa1;
        *(float4*)&Bst[lr][lc]      = pb0;
        *(float4*)&Bst[lr][lc + 64] = pb1;
        __syncthreads();
        if (s < DD / 16 - 1) {
            size_t ro = (size_t)((s + 1) * 16 + lr) * PPAD;
            pa0 = *(const float4*)(Abase + ro + lc);
            pa1 = *(const float4*)(Abase + ro + lc + 64);
            pb0 = *(const float4*)(Bbase + ro + lc);
            pb1 = *(const float4*)(Bbase + ro + lc + 64);
        }
        #pragma unroll
        for (int k = 0; k < 16; k++) {
            float4 a0 = *(const float4*)&Ast[k][ty * 8];
            float4 a1 = *(const float4*)&Ast[k][ty * 8 + 4];
            ulonglong2 b0 = *(const ulonglong2*)&Bst[k][tx * 4];
            ulonglong2 b1 = *(const ulonglong2*)&Bst[k][64 + tx * 4];
            float av[8] = {a0.x, a0.y, a0.z, a0.w, a1.x, a1.y, a1.z, a1.w};
            #pragma unroll
            for (int i = 0; i < 8; i++) {
                unsigned long long ap = pack2(av[i]);
                fma2(acc[i][0], ap, b0.x);
                fma2(acc[i][1], ap, b0.y);
                fma2(acc[i][2], ap, b1.x);
                fma2(acc[i][3], ap, b1.y);
            }
        }
    }

    // epilogue: best candidate per query row
    #pragma unroll
    for (int i = 0; i < 8; i++) {
        int m = ty * 8 + i;
        unsigned long long best = 0ull;
        if (qs[m] >= 0) {
            #pragma unroll
            for (int j = 0; j < 4; j++) {
                float2 v = unpack2(acc[i][j]);
                int cbase = cb * 128 + ((j < 2) ? 0 : 64) + tx * 4 + (j & 1) * 2;
                #pragma unroll
                for (int e = 0; e < 2; e++) {
                    int cand = cbase + e;
                    if (cand < NP && !g_excl[cand]) {
                        float sc = (e ? v.y : v.x) * g_invnorm[cand];
                        unsigned long long key =
                            ((unsigned long long)mono(sc) << 32) | (unsigned)(~cand);
                        if (key > best) best = key;
                    }
                }
            }
        }
        red[m][tx] = best;
    }
    __syncthreads();
    if (tid < 128) {
        unsigned long long b = red[tid][0];
        #pragma unroll
        for (int t = 1; t < 16; t++) { unsigned long long v = red[tid][t]; if (v > b) b = v; }
        if (b != 0ull && qs[tid] >= 0)
            atomicMax(&g_keys[qs[tid]], b);
    }
}

// ---------------- K6: output assembly (gather-side overlap-average) ----------
__global__ void output_kernel(const float* __restrict__ low,
                              float* __restrict__ out) {
    int idx = blockIdx.x * blockDim.x + threadIdx.x;
    if (idx >= CC * HH * WW) return;
    int c   = idx / (HH * WW);
    int rem = idx - c * (HH * WW);
    int y = rem / WW, x = rem % WW;

    int ilo = y - (KK - 1); if (ilo < 0) ilo = 0;
    int ihi = y; if (ihi > HP - 1) ihi = HP - 1;
    int jlo = x - (KK - 1); if (jlo < 0) jlo = 0;
    int jhi = x; if (jhi > HP - 1) jhi = HP - 1;

    float cnt = 0.f, accv = 0.f;
    for (int i = ilo; i <= ihi; i++) {
        for (int j = jlo; j <= jhi; j++) {
            int p = i * HP + j;
            if (g_valid[p]) {
                cnt += 1.0f;
                unsigned bp = (unsigned)(~g_keys[p]);  // low 32 bits = ~cand
                int bi = bp / HP, bj = bp % HP;
                accv += low[c * (HH * WW) + (bi + y - i) * WW + (bj + x - j)];
            }
        }
    }
    out[idx] = (cnt != 0.f) ? (accv / (cnt + EPSF)) : low[idx];
}

// ---------------- launcher ---------------------------------------------------
extern "C" void kernel_launch(void* const* d_in, const int* in_sizes, int n_in,
                              void* d_out, int out_size) {
    const float* low  = (const float*)d_in[0];
    const float* high = (const float*)d_in[1];
    const int*   mask = (const int*)d_in[2];
    float*       out  = (float*)d_out;

    sumsq_kernel<<<(HH * WW + 255) / 256, 256>>>(low);
    extractT_kernel<<<dim3((NP + 255) / 256, DD), 256>>>(low);
    stats_kernel<<<(NP + 255) / 256, 256>>>(mask);
    gather_high_kernel<<<dim3(2, DD), 256>>>(high);
    gemm_argmax_kernel<<<dim3((NP + 127) / 128, (NP + 127) / 128), 256>>>();
    output_kernel<<<(CC * HH * WW + 255) / 256, 256>>>(low, out);
}

// round 3
// speedup vs baseline: 1.6869x; 1.6869x over previous
#include <cuda_runtime.h>
#include <cstdint>

// Problem constants
#define CC   32
#define HH   80
#define WW   80
#define KK   4
#define HP   77            // HH-KK+1
#define NP   (HP*HP)       // 5929 patches
#define DD   (CC*KK*KK)    // 512
#define MW   81            // mask width (H+1)
#define EPSF 1e-6f
#define PPAD 6016          // padded column stride (>= NP, 16B aligned)
#define HW   (HH*WW)

// ---------------- device scratch (allocation-free rule) ----------------------
__device__ float              g_lowpT [DD * PPAD];   // compacted candidates, k-major [D][ci]
__device__ float              g_highTc[DD * PPAD];   // compacted queries,    k-major [D][qi]
__device__ float              g_s1[HW];              // per-pixel sum over c of low^2
__device__ float              g_invnorm[NP];
__device__ unsigned char      g_valid[NP];
__device__ unsigned long long g_keys[NP];
__device__ int                g_qlist[NP];
__device__ int                g_clist[NP];
__device__ int                g_qcount;
__device__ int                g_ccount;

// monotone float->uint mapping (order-preserving for all finite floats)
__device__ __forceinline__ unsigned mono(float f) {
    unsigned b = __float_as_uint(f);
    return (b & 0x80000000u) ? ~b : (b | 0x80000000u);
}

// ---------------- K1: per-pixel channel sum of squares (+ counter reset) -----
__global__ void sumsq_kernel(const float* __restrict__ low) {
    int pix = blockIdx.x * blockDim.x + threadIdx.x;
    if (pix == 0) { g_qcount = 0; g_ccount = 0; }
    if (pix >= HW) return;
    float s = 0.f;
    #pragma unroll
    for (int c = 0; c < CC; c++) { float v = low[c * HW + pix]; s += v * v; }
    g_s1[pix] = s;
}

// ---------------- K2: per-patch stats (norm, valid, compaction lists) --------
__global__ void stats_kernel(const int* __restrict__ mask) {
    int p = blockIdx.x * blockDim.x + threadIdx.x;
    if (p >= NP) return;
    int pi = p / HP, pj = p % HP;
    float ns = 0.f;
    #pragma unroll
    for (int di = 0; di < KK; di++)
        #pragma unroll
        for (int dj = 0; dj < KK; dj++)
            ns += g_s1[(pi + di) * WW + (pj + dj)];
    g_invnorm[p] = 1.0f / (sqrtf(ns) + EPSF);
    g_keys[p] = ((unsigned long long)mono(-1e9f) << 32) | 0xFFFFFFFFull; // cand=0 fallback
    int m00 = mask[pi * MW + pj];
    // candidate: not excluded (mask != 1)
    if (m00 != 1) {
        int slot = atomicAdd(&g_ccount, 1);
        g_clist[slot] = p;
    }
    // query: all 4 corners nonzero
    int v = (m00 != 0) && (mask[pi * MW + pj + KK] != 0) &&
            (mask[(pi + KK) * MW + pj] != 0) && (mask[(pi + KK) * MW + pj + KK] != 0);
    g_valid[p] = (unsigned char)v;
    if (v) {
        int slot = atomicAdd(&g_qcount, 1);
        g_qlist[slot] = p;
    }
}

// ---------------- K3: gather compacted candidate matrix, k-major -------------
__global__ void gather_low_kernel(const float* __restrict__ low) {
    int nc = g_ccount;
    int d  = blockIdx.y;
    int c  = d >> 4, di = (d >> 2) & 3, dj = d & 3;
    for (int ci = blockIdx.x * blockDim.x + threadIdx.x; ci < nc;
         ci += gridDim.x * blockDim.x) {
        int p  = g_clist[ci];
        int pi = p / HP, pj = p % HP;
        g_lowpT[d * PPAD + ci] = low[c * HW + (pi + di) * WW + (pj + dj)];
    }
}

// ---------------- K4: gather compacted query matrix, k-major -----------------
__global__ void gather_high_kernel(const float* __restrict__ high) {
    int nq = g_qcount;
    int d  = blockIdx.y;
    int c  = d >> 4, di = (d >> 2) & 3, dj = d & 3;
    for (int qi = blockIdx.x * blockDim.x + threadIdx.x; qi < nq;
         qi += gridDim.x * blockDim.x) {
        int p  = g_qlist[qi];
        int pi = p / HP, pj = p % HP;
        g_highTc[d * PPAD + qi] = high[c * HW + (pi + di) * WW + (pj + dj)];
    }
}

// ---------------- K5: persistent 128x64 GEMM + fused argmax ------------------
// 256 threads, 8 queries x 4 candidates per thread, shuffle-reduced epilogue.
__global__ void __launch_bounds__(256, 2) gemm_argmax_kernel() {
    const int nq = g_qcount;
    const int nc = g_ccount;
    const int qt = (nq + 127) >> 7;
    const int ct = (nc + 63) >> 6;
    const int ntiles = qt * ct;

    __shared__ float Ast[16][128];         // k-major query tile
    __shared__ float Bst[16][64];          // k-major candidate tile
    __shared__ int   qs[128];              // orig query ids for this tile
    __shared__ int   cs[64];               // orig candidate ids
    __shared__ float is[64];               // invnorm per candidate col

    const int tid = threadIdx.x;
    const int ty = tid >> 4, tx = tid & 15;
    const int lr = tid >> 4;               // loader row 0..15
    const int lc = (tid & 15) * 4;         // loader col chunk

    for (int t = blockIdx.x; t < ntiles; t += gridDim.x) {
        const int qb = t / ct;
        const int cb = t - qb * ct;

        __syncthreads();                   // previous tile's smem reads done
        if (tid < 128) {
            int qi = qb * 128 + tid;
            qs[tid] = (qi < nq) ? g_qlist[qi] : -1;
        }
        if (tid < 64) {
            int ci = cb * 64 + tid;
            int co = (ci < nc) ? g_clist[ci] : 0;
            cs[tid] = co;
            is[tid] = (ci < nc) ? g_invnorm[co] : 0.f;
        }

        const float* Abase = g_highTc + qb * 128;
        const float* Bbase = g_lowpT  + cb * 64;

        float acc[8][4];
        #pragma unroll
        for (int i = 0; i < 8; i++)
            #pragma unroll
            for (int j = 0; j < 4; j++) acc[i][j] = 0.f;

        float4 pa0 = *(const float4*)(Abase + (size_t)lr * PPAD + lc);
        float4 pa1 = *(const float4*)(Abase + (size_t)lr * PPAD + lc + 64);
        float4 pb0 = *(const float4*)(Bbase + (size_t)lr * PPAD + lc);

        for (int s = 0; s < DD / 16; s++) {
            __syncthreads();
            *(float4*)&Ast[lr][lc]      = pa0;
            *(float4*)&Ast[lr][lc + 64] = pa1;
            *(float4*)&Bst[lr][lc]      = pb0;
            __syncthreads();
            if (s < DD / 16 - 1) {
                size_t ro = (size_t)((s + 1) * 16 + lr) * PPAD;
                pa0 = *(const float4*)(Abase + ro + lc);
                pa1 = *(const float4*)(Abase + ro + lc + 64);
                pb0 = *(const float4*)(Bbase + ro + lc);
            }
            #pragma unroll
            for (int k = 0; k < 16; k++) {
                float4 a0 = *(const float4*)&Ast[k][ty * 8];
                float4 a1 = *(const float4*)&Ast[k][ty * 8 + 4];
                float4 b  = *(const float4*)&Bst[k][tx * 4];
                float av[8] = {a0.x, a0.y, a0.z, a0.w, a1.x, a1.y, a1.z, a1.w};
                float bv[4] = {b.x, b.y, b.z, b.w};
                #pragma unroll
                for (int i = 0; i < 8; i++)
                    #pragma unroll
                    for (int j = 0; j < 4; j++)
                        acc[i][j] = fmaf(av[i], bv[j], acc[i][j]);
            }
        }

        // epilogue: per-query-row argmax via 16-lane shuffle reduction
        int   corig[4];
        float cinv[4];
        bool  cok[4];
        #pragma unroll
        for (int j = 0; j < 4; j++) {
            int cc = cb * 64 + tx * 4 + j;
            cok[j]   = (cc < nc);
            corig[j] = cs[tx * 4 + j];
            cinv[j]  = is[tx * 4 + j];
        }
        #pragma unroll
        for (int i = 0; i < 8; i++) {
            int m = ty * 8 + i;
            int qorig = qs[m];
            unsigned long long best = 0ull;
            #pragma unroll
            for (int j = 0; j < 4; j++) {
                if (cok[j]) {
                    float sc = acc[i][j] * cinv[j];
                    unsigned long long key =
                        ((unsigned long long)mono(sc) << 32) | (unsigned)(~corig[j]);
                    if (key > best) best = key;
                }
            }
            #pragma unroll
            for (int o = 8; o; o >>= 1) {
                unsigned long long v = __shfl_xor_sync(0xFFFFFFFFu, best, o);
                if (v > best) best = v;
            }
            if (tx == 0 && qorig >= 0 && best != 0ull)
                atomicMax(&g_keys[qorig], best);
        }
    }
}

// ---------------- K6: output assembly, thread = (pixel, 8-channel group) -----
__global__ void output_kernel(const float* __restrict__ low,
                              float* __restrict__ out) {
    int pix = blockIdx.x * blockDim.x + threadIdx.x;
    if (pix >= HW) return;
    int y = pix / WW, x = pix % WW;
    int c0 = blockIdx.y * 8;

    int   offr[16];
    bool  ok[16];
    float cnt = 0.f;
    #pragma unroll
    for (int t = 0; t < 16; t++) {
        int di = t >> 2, dj = t & 3;
        int i = y - di, j = x - dj;
        bool o = (i >= 0) && (i < HP) && (j >= 0) && (j < HP);
        int p = o ? (i * HP + j) : 0;
        o = o && g_valid[p];
        ok[t] = o;
        int off = 0;
        if (o) {
            unsigned bp = (unsigned)(~g_keys[p]);   // low 32 bits = ~best_cand
            int bi = bp / HP, bj = bp % HP;
            off = (bi + di) * WW + (bj + dj);
            cnt += 1.f;
        }
        offr[t] = off;
    }

    if (cnt == 0.f) {
        #pragma unroll
        for (int c = 0; c < 8; c++)
            out[(c0 + c) * HW + pix] = low[(c0 + c) * HW + pix];
        return;
    }
    float inv = 1.f / (cnt + EPSF);
    #pragma unroll
    for (int c = 0; c < 8; c++) {
        const float* lc = low + (c0 + c) * HW;
        float a = 0.f;
        #pragma unroll
        for (int t = 0; t < 16; t++)
            if (ok[t]) a += lc[offr[t]];
        out[(c0 + c) * HW + pix] = a * inv;
    }
}

// ---------------- launcher ---------------------------------------------------
extern "C" void kernel_launch(void* const* d_in, const int* in_sizes, int n_in,
                              void* d_out, int out_size) {
    const float* low  = (const float*)d_in[0];
    const float* high = (const float*)d_in[1];
    const int*   mask = (const int*)d_in[2];
    float*       out  = (float*)d_out;

    sumsq_kernel<<<(HW + 255) / 256, 256>>>(low);
    stats_kernel<<<(NP + 255) / 256, 256>>>(mask);
    gather_low_kernel<<<dim3(6, DD), 256>>>(low);
    gather_high_kernel<<<dim3(2, DD), 256>>>(high);
    gemm_argmax_kernel<<<296, 256>>>();
    output_kernel<<<dim3((HW + 255) / 256, 4), 256>>>(low, out);
}